// round 9
// baseline (speedup 1.0000x reference)
#include <cuda_runtime.h>
#include <cstdint>

#define NN 50000
#define NE 800000
constexpr float NEG_SLOPE = 0.2f;

// ---------------- scratch (device globals; no allocation) ----------------
__device__ float g_h  [NN * 256];
__device__ float g_z1 [NN * 256];
__device__ float g_z2 [NN * 32];
__device__ float g_r1 [NN * 256];
__device__ float g_als[NN * 8];
__device__ float g_ald[NN * 8];
__device__ int   g_deg[NN];
__device__ int   g_cnt[NN];
__device__ int   g_off[NN + 1];
__device__ int   g_csr[NE + NN];

// ---------------- f32x2 helpers (sm_100-family packed fp32) ----------------
__device__ __forceinline__ void ffma2(unsigned long long& d, unsigned long long a,
                                      unsigned long long b) {
    asm("fma.rn.f32x2 %0, %1, %2, %3;" : "=l"(d) : "l"(a), "l"(b), "l"(d));
}
__device__ __forceinline__ unsigned long long dup2(float x) {
    unsigned long long r;
    uint32_t u = __float_as_uint(x);
    asm("mov.b64 %0, {%1, %1};" : "=l"(r) : "r"(u));
    return r;
}
__device__ __forceinline__ float2 unpack2(unsigned long long v) {
    uint32_t lo, hi;
    asm("mov.b64 {%0, %1}, %2;" : "=r"(lo), "=r"(hi) : "l"(v));
    return make_float2(__uint_as_float(lo), __uint_as_float(hi));
}

// ================= CSR build =================
__global__ void hist_kernel(const int* __restrict__ ei, int* __restrict__ deg) {
    int e = blockIdx.x * blockDim.x + threadIdx.x;
    if (e < NE) atomicAdd(&deg[ei[NE + e]], 1);
}

__global__ void scan_kernel(const int* __restrict__ deg, int* __restrict__ off) {
    __shared__ int wsum[32];
    __shared__ int carry_s;
    int tid = threadIdx.x, lane = tid & 31, wid = tid >> 5;
    if (tid == 0) { carry_s = 0; off[0] = 0; }
    __syncthreads();
    for (int base = 0; base < NN; base += 1024) {
        int i = base + tid;
        int v = (i < NN) ? deg[i] + 1 : 0;
        int x = v;
#pragma unroll
        for (int o = 1; o < 32; o <<= 1) {
            int t = __shfl_up_sync(0xffffffffu, x, o);
            if (lane >= o) x += t;
        }
        if (lane == 31) wsum[wid] = x;
        __syncthreads();
        if (wid == 0) {
            int y = wsum[lane];
#pragma unroll
            for (int o = 1; o < 32; o <<= 1) {
                int t = __shfl_up_sync(0xffffffffu, y, o);
                if (lane >= o) y += t;
            }
            wsum[lane] = y;
        }
        __syncthreads();
        int incl = x + (wid > 0 ? wsum[wid - 1] : 0) + carry_s;
        if (i < NN) off[i + 1] = incl;
        __syncthreads();
        if (tid == 1023) carry_s = incl;
        __syncthreads();
    }
}

__global__ void scatter_kernel(const int* __restrict__ ei, const int* __restrict__ off,
                               int* __restrict__ cnt, int* __restrict__ csr) {
    int e = blockIdx.x * blockDim.x + threadIdx.x;
    if (e < NE) {
        int d = ei[NE + e];
        int pos = off[d] + atomicAdd(&cnt[d], 1);
        csr[pos] = ei[e];
    } else if (e < NE + NN) {
        int n = e - NE;
        csr[off[n + 1] - 1] = n;  // self loop in last slot
    }
}

// ============ SGEMM with FFMA2: C[N,M] = A[N,K] @ B[K,M] ============
template <int BM, int BN, int BK, int TM, int TN>
__global__ void __launch_bounds__((BM / TM) * (BN / TN))
sgemm2_kernel(int N, int K, int M,
              const float* __restrict__ A, const float* __restrict__ B,
              float* __restrict__ C) {
    constexpr int TX = BN / TN;
    constexpr int TY = BM / TM;
    constexpr int THREADS = TX * TY;
    constexpr int TN2 = TN / 2;

    __shared__ float As[BK][BM];
    __shared__ float Bs[BK][BN];

    const int tid = threadIdx.x;
    const int tx = tid % TX;
    const int ty = tid / TX;
    const int row0 = blockIdx.x * BM;
    const int col0 = blockIdx.y * BN;

    unsigned long long acc2[TM][TN2];
#pragma unroll
    for (int m = 0; m < TM; m++)
#pragma unroll
        for (int n = 0; n < TN2; n++) acc2[m][n] = 0ull;

    for (int k0 = 0; k0 < K; k0 += BK) {
        // load A tile (transposed into smem)
#pragma unroll
        for (int i = tid * 4; i < BM * BK; i += THREADS * 4) {
            int r = i / BK;
            int kk = i % BK;
            float4 v = make_float4(0.f, 0.f, 0.f, 0.f);
            if (row0 + r < N)
                v = *(const float4*)&A[(size_t)(row0 + r) * K + k0 + kk];
            As[kk + 0][r] = v.x;
            As[kk + 1][r] = v.y;
            As[kk + 2][r] = v.z;
            As[kk + 3][r] = v.w;
        }
        // load B tile
#pragma unroll
        for (int i = tid * 4; i < BK * BN; i += THREADS * 4) {
            int kk = i / BN;
            int c = i % BN;
            *(float4*)&Bs[kk][c] = *(const float4*)&B[(size_t)(k0 + kk) * M + col0 + c];
        }
        __syncthreads();

#pragma unroll
        for (int kk = 0; kk < BK; kk++) {
            float ra[TM];
#pragma unroll
            for (int m = 0; m < TM; m += 4)
                *(float4*)&ra[m] = *(const float4*)&As[kk][ty * TM + m];
            unsigned long long a2[TM];
#pragma unroll
            for (int m = 0; m < TM; m++) a2[m] = dup2(ra[m]);
            unsigned long long b2[TN2];
#pragma unroll
            for (int n = 0; n < TN2; n += 2) {
                ulonglong2 bv = *(const ulonglong2*)&Bs[kk][tx * TN + n * 2];
                b2[n] = bv.x;
                b2[n + 1] = bv.y;
            }
#pragma unroll
            for (int m = 0; m < TM; m++)
#pragma unroll
                for (int n = 0; n < TN2; n++) ffma2(acc2[m][n], a2[m], b2[n]);
        }
        __syncthreads();
    }

#pragma unroll
    for (int m = 0; m < TM; m++) {
        int r = row0 + ty * TM + m;
        if (r < N) {
#pragma unroll
            for (int n = 0; n < TN2; n += 2) {
                float2 p0 = unpack2(acc2[m][n]);
                float2 p1 = unpack2(acc2[m][n + 1]);
                float4 v = make_float4(p0.x, p0.y, p1.x, p1.y);
                *(float4*)&C[(size_t)r * M + col0 + tx * TN + n * 2] = v;
            }
        }
    }
}

// ======= layer-3 special: h = z2 @ W3 (K=32, M=256) fused with attn coeffs ======
// warp per node (4 nodes per warp, strided); W3 + as3/ad3 staged in smem.
__global__ void __launch_bounds__(256)
gemm32_attn_kernel(const float* __restrict__ z2, const float* __restrict__ W3,
                   const float* __restrict__ as3, const float* __restrict__ ad3,
                   float* __restrict__ h, float* __restrict__ als,
                   float* __restrict__ ald) {
    __shared__ float W3s[32 * 256];
    __shared__ float as3s[256];
    __shared__ float ad3s[256];
    int tid = threadIdx.x;
#pragma unroll
    for (int p = 0; p < 8; p++)
        ((float4*)W3s)[tid + p * 256] = ((const float4*)W3)[tid + p * 256];
    if (tid < 64) ((float4*)as3s)[tid] = ((const float4*)as3)[tid];
    else if (tid < 128) ((float4*)ad3s)[tid - 64] = ((const float4*)ad3)[tid - 64];
    __syncthreads();

    int wid = tid >> 5, lane = tid & 31;
    int hd = lane >> 2;
    const float4* W3s4 = (const float4*)W3s;
    const float4* as4 = (const float4*)as3s;
    const float4* ad4 = (const float4*)ad3s;

#pragma unroll
    for (int t = 0; t < 4; t++) {
        int node = blockIdx.x * 32 + wid + t * 8;
        if (node >= NN) return;
        float z = z2[(size_t)node * 32 + lane];
        float4 a0 = make_float4(0, 0, 0, 0), a1 = make_float4(0, 0, 0, 0);
#pragma unroll
        for (int k = 0; k < 32; k++) {
            float zk = __shfl_sync(0xffffffffu, z, k);
            float4 w0 = W3s4[k * 64 + lane * 2];
            float4 w1 = W3s4[k * 64 + lane * 2 + 1];
            a0.x += zk * w0.x; a0.y += zk * w0.y; a0.z += zk * w0.z; a0.w += zk * w0.w;
            a1.x += zk * w1.x; a1.y += zk * w1.y; a1.z += zk * w1.z; a1.w += zk * w1.w;
        }
        float4* hp = (float4*)(h + (size_t)node * 256);
        hp[lane * 2] = a0;
        hp[lane * 2 + 1] = a1;
        float4 s0 = as4[hd * 8 + (lane & 3) * 2], s1 = as4[hd * 8 + (lane & 3) * 2 + 1];
        float4 d0 = ad4[hd * 8 + (lane & 3) * 2], d1 = ad4[hd * 8 + (lane & 3) * 2 + 1];
        float s = a0.x * s0.x + a0.y * s0.y + a0.z * s0.z + a0.w * s0.w
                + a1.x * s1.x + a1.y * s1.y + a1.z * s1.z + a1.w * s1.w;
        float d = a0.x * d0.x + a0.y * d0.y + a0.z * d0.z + a0.w * d0.w
                + a1.x * d1.x + a1.y * d1.y + a1.z * d1.z + a1.w * d1.w;
        s += __shfl_xor_sync(0xffffffffu, s, 1);
        s += __shfl_xor_sync(0xffffffffu, s, 2);
        d += __shfl_xor_sync(0xffffffffu, d, 1);
        d += __shfl_xor_sync(0xffffffffu, d, 2);
        if ((lane & 3) == 0) {
            als[(size_t)node * 8 + hd] = s;
            ald[(size_t)node * 8 + hd] = d;
        }
    }
}

// ================= attention coefficients: als/ald [N,H] =================
template <int H, int C>
__global__ void attn_kernel(const float* __restrict__ h,
                            const float* __restrict__ asr,
                            const float* __restrict__ adr,
                            float* __restrict__ als, float* __restrict__ ald) {
    int idx = blockIdx.x * blockDim.x + threadIdx.x;  // = n*H + head
    if (idx >= NN * H) return;
    int hd = idx % H;
    const float4* hv = (const float4*)(h + (size_t)idx * C);
    const float4* av = (const float4*)(asr + hd * C);
    const float4* dv = (const float4*)(adr + hd * C);
    float s = 0.f, d = 0.f;
#pragma unroll
    for (int i = 0; i < C / 4; i++) {
        float4 x = hv[i], a = av[i], b = dv[i];
        s += x.x * a.x + x.y * a.y + x.z * a.z + x.w * a.w;
        d += x.x * b.x + x.y * b.y + x.z * b.z + x.w * b.w;
    }
    als[idx] = s;
    ald[idx] = d;
}

// ================= CSR aggregation (softmax-normalized), fused bias/relu =======
template <bool RELU>
__global__ void __launch_bounds__(256)
agg8_kernel(const int* __restrict__ off, const int* __restrict__ csr,
            const float* __restrict__ h, const float* __restrict__ als,
            const float* __restrict__ ald, const float* __restrict__ b,
            float* __restrict__ out) {
    int node = blockIdx.x * 8 + (threadIdx.x >> 5);
    if (node >= NN) return;
    int lane = threadIdx.x & 31;
    int hl = lane >> 3, hh = hl + 4;
    float aldl = ald[node * 8 + hl], aldh = ald[node * 8 + hh];
    float4 accl = make_float4(0, 0, 0, 0), acch = make_float4(0, 0, 0, 0);
    float wsl = 0.f, wsh = 0.f;
    int s0 = off[node], s1 = off[node + 1];
    for (int i = s0; i < s1; i++) {
        int src = __ldg(&csr[i]);
        const float4* hs = (const float4*)(h + (size_t)src * 256);
        float el = __ldg(&als[src * 8 + hl]) + aldl;
        float eh = __ldg(&als[src * 8 + hh]) + aldh;
        el = el > 0.f ? el : NEG_SLOPE * el;
        eh = eh > 0.f ? eh : NEG_SLOPE * eh;
        float wl = __expf(el), wh = __expf(eh);
        float4 h1 = hs[lane], h2 = hs[lane + 32];
        accl.x += wl * h1.x; accl.y += wl * h1.y; accl.z += wl * h1.z; accl.w += wl * h1.w;
        acch.x += wh * h2.x; acch.y += wh * h2.y; acch.z += wh * h2.z; acch.w += wh * h2.w;
        wsl += wl; wsh += wh;
    }
    float invl = 1.f / wsl, invh = 1.f / wsh;
    float4 b1 = ((const float4*)b)[lane], b2 = ((const float4*)b)[lane + 32];
    float4 o1 = make_float4(accl.x * invl + b1.x, accl.y * invl + b1.y,
                            accl.z * invl + b1.z, accl.w * invl + b1.w);
    float4 o2 = make_float4(acch.x * invh + b2.x, acch.y * invh + b2.y,
                            acch.z * invh + b2.z, acch.w * invh + b2.w);
    if (RELU) {
        o1.x = fmaxf(o1.x, 0.f); o1.y = fmaxf(o1.y, 0.f);
        o1.z = fmaxf(o1.z, 0.f); o1.w = fmaxf(o1.w, 0.f);
        o2.x = fmaxf(o2.x, 0.f); o2.y = fmaxf(o2.y, 0.f);
        o2.z = fmaxf(o2.z, 0.f); o2.w = fmaxf(o2.w, 0.f);
    }
    float4* op = (float4*)(out + (size_t)node * 256);
    op[lane] = o1;
    op[lane + 32] = o2;
}

__global__ void __launch_bounds__(256)
agg1c32_kernel(const int* __restrict__ off, const int* __restrict__ csr,
               const float* __restrict__ h, const float* __restrict__ als,
               const float* __restrict__ ald, const float* __restrict__ b,
               float* __restrict__ out) {
    int node = blockIdx.x * 8 + (threadIdx.x >> 5);
    if (node >= NN) return;
    int lane = threadIdx.x & 31, sub = lane >> 3, col = lane & 7;
    float aldn = ald[node];
    float4 acc = make_float4(0, 0, 0, 0);
    float ws = 0.f;
    int s0 = off[node], s1 = off[node + 1];
    for (int i = s0 + sub; i < s1; i += 4) {
        int src = __ldg(&csr[i]);
        float e = __ldg(&als[src]) + aldn;
        e = e > 0.f ? e : NEG_SLOPE * e;
        float w = __expf(e);
        float4 hv = ((const float4*)(h + (size_t)src * 32))[col];
        acc.x += w * hv.x; acc.y += w * hv.y; acc.z += w * hv.z; acc.w += w * hv.w;
        ws += w;
    }
#pragma unroll
    for (int m = 8; m <= 16; m <<= 1) {
        acc.x += __shfl_xor_sync(0xffffffffu, acc.x, m);
        acc.y += __shfl_xor_sync(0xffffffffu, acc.y, m);
        acc.z += __shfl_xor_sync(0xffffffffu, acc.z, m);
        acc.w += __shfl_xor_sync(0xffffffffu, acc.w, m);
        ws    += __shfl_xor_sync(0xffffffffu, ws, m);
    }
    if (sub == 0) {
        float inv = 1.f / ws;
        float4 bb = ((const float4*)b)[col];
        float4 o = make_float4(acc.x * inv + bb.x, acc.y * inv + bb.y,
                               acc.z * inv + bb.z, acc.w * inv + bb.w);
        ((float4*)(out + (size_t)node * 32))[col] = o;
    }
}

__global__ void __launch_bounds__(256)
agg1c128_kernel(const int* __restrict__ off, const int* __restrict__ csr,
                const float* __restrict__ h, const float* __restrict__ als,
                const float* __restrict__ ald, const float* __restrict__ b,
                float* __restrict__ out) {
    int node = blockIdx.x * 8 + (threadIdx.x >> 5);
    if (node >= NN) return;
    int lane = threadIdx.x & 31;
    float aldn = ald[node];
    float4 acc = make_float4(0, 0, 0, 0);
    float ws = 0.f;
    int s0 = off[node], s1 = off[node + 1];
    for (int i = s0; i < s1; i++) {
        int src = __ldg(&csr[i]);
        float e = __ldg(&als[src]) + aldn;
        e = e > 0.f ? e : NEG_SLOPE * e;
        float w = __expf(e);
        float4 hv = ((const float4*)(h + (size_t)src * 128))[lane];
        acc.x += w * hv.x; acc.y += w * hv.y; acc.z += w * hv.z; acc.w += w * hv.w;
        ws += w;
    }
    float inv = 1.f / ws;
    float4 bb = ((const float4*)b)[lane];
    float4 o = make_float4(acc.x * inv + bb.x, acc.y * inv + bb.y,
                           acc.z * inv + bb.z, acc.w * inv + bb.w);
    ((float4*)(out + (size_t)node * 128))[lane] = o;
}

// ================= launch =================
static inline int ceil_div_i(long long a, long long b) { return (int)((a + b - 1) / b); }

extern "C" void kernel_launch(void* const* d_in, const int* in_sizes, int n_in,
                              void* d_out, int out_size) {
    const float* x = (const float*)d_in[0];
    const int* ei = (const int*)d_in[1];   // int32 (JAX x64 disabled)
    const float* W1 = (const float*)d_in[2];
    const float* as1 = (const float*)d_in[3];
    const float* ad1 = (const float*)d_in[4];
    const float* b1 = (const float*)d_in[5];
    const float* W2 = (const float*)d_in[6];
    const float* as2 = (const float*)d_in[7];
    const float* ad2 = (const float*)d_in[8];
    const float* b2 = (const float*)d_in[9];
    const float* W3 = (const float*)d_in[10];
    const float* as3 = (const float*)d_in[11];
    const float* ad3 = (const float*)d_in[12];
    const float* b3 = (const float*)d_in[13];
    const float* W4 = (const float*)d_in[14];
    const float* as4 = (const float*)d_in[15];
    const float* ad4 = (const float*)d_in[16];
    const float* b4 = (const float*)d_in[17];
    float* out = (float*)d_out;

    float *h, *z1, *z2, *r1, *als, *ald;
    int *deg, *cnt, *off, *csr;
    cudaGetSymbolAddress((void**)&h, g_h);
    cudaGetSymbolAddress((void**)&z1, g_z1);
    cudaGetSymbolAddress((void**)&z2, g_z2);
    cudaGetSymbolAddress((void**)&r1, g_r1);
    cudaGetSymbolAddress((void**)&als, g_als);
    cudaGetSymbolAddress((void**)&ald, g_ald);
    cudaGetSymbolAddress((void**)&deg, g_deg);
    cudaGetSymbolAddress((void**)&cnt, g_cnt);
    cudaGetSymbolAddress((void**)&off, g_off);
    cudaGetSymbolAddress((void**)&csr, g_csr);

    const int TPB = 256;
    const int rowBlocks = ceil_div_i(NN, 128);
    const int aggBlocks = ceil_div_i(NN, 8);

    // ---- CSR build (by dst), reused by all 4 layers ----
    cudaMemsetAsync(deg, 0, NN * sizeof(int), 0);
    cudaMemsetAsync(cnt, 0, NN * sizeof(int), 0);
    hist_kernel<<<ceil_div_i(NE, TPB), TPB>>>(ei, deg);
    scan_kernel<<<1, 1024>>>(deg, off);
    scatter_kernel<<<ceil_div_i(NE + NN, TPB), TPB>>>(ei, off, cnt, csr);

    // ===== Layer 1: 128 -> [8 x 32], relu =====
    sgemm2_kernel<128, 128, 8, 8, 8><<<dim3(rowBlocks, 2), 256>>>(NN, 128, 256, x, W1, h);
    attn_kernel<8, 32><<<ceil_div_i((long long)NN * 8, TPB), TPB>>>(h, as1, ad1, als, ald);
    agg8_kernel<true><<<aggBlocks, TPB>>>(off, csr, h, als, ald, b1, z1);

    // ===== Layer 2: 256 -> 32 =====
    sgemm2_kernel<128, 32, 16, 8, 4><<<dim3(rowBlocks, 1), 128>>>(NN, 256, 32, z1, W2, h);
    attn_kernel<1, 32><<<ceil_div_i(NN, TPB), TPB>>>(h, as2, ad2, als, ald);
    agg1c32_kernel<<<aggBlocks, TPB>>>(off, csr, h, als, ald, b2, z2);

    // ===== Layer 3: 32 -> [8 x 32], relu (small-K kernel, fused attn) =====
    gemm32_attn_kernel<<<ceil_div_i(NN, 32), 256>>>(z2, W3, as3, ad3, h, als, ald);
    agg8_kernel<true><<<aggBlocks, TPB>>>(off, csr, h, als, ald, b3, r1);

    // ===== Layer 4: 256 -> 128 =====
    sgemm2_kernel<128, 128, 8, 8, 8><<<dim3(rowBlocks, 1), 256>>>(NN, 256, 128, r1, W4, h);
    attn_kernel<1, 128><<<ceil_div_i(NN, TPB), TPB>>>(h, as4, ad4, als, ald);
    agg1c128_kernel<<<aggBlocks, TPB>>>(off, csr, h, als, ald, b4, out);
}

// round 10
// speedup vs baseline: 1.2919x; 1.2919x over previous
#include <cuda_runtime.h>
#include <cstdint>

#define NN 50000
#define NE 800000
constexpr float NEG_SLOPE = 0.2f;

// ---------------- scratch (device globals; no allocation) ----------------
__device__ float g_h  [NN * 256];
__device__ float g_z1 [NN * 256];
__device__ float g_z2 [NN * 32];
__device__ float g_r1 [NN * 256];
__device__ float g_als[NN * 8];
__device__ float g_ald[NN * 8];
__device__ int   g_deg[NN];
__device__ int   g_cnt[NN];
__device__ int   g_off[NN + 1];
__device__ int   g_csr[NE + NN];

// ---------------- tf32 helpers ----------------
__device__ __forceinline__ uint32_t f2tf(float f) {
    uint32_t r;
    asm("cvt.rna.tf32.f32 %0, %1;" : "=r"(r) : "f"(f));
    return r;
}
__device__ __forceinline__ void mma_tf32(float* c, const uint32_t* a, const uint32_t* b) {
    asm volatile(
        "mma.sync.aligned.m16n8k8.row.col.f32.tf32.tf32.f32 "
        "{%0,%1,%2,%3}, {%4,%5,%6,%7}, {%8,%9}, {%0,%1,%2,%3};"
        : "+f"(c[0]), "+f"(c[1]), "+f"(c[2]), "+f"(c[3])
        : "r"(a[0]), "r"(a[1]), "r"(a[2]), "r"(a[3]), "r"(b[0]), "r"(b[1]));
}

// ================= CSR build =================
__global__ void hist_kernel(const int* __restrict__ ei, int* __restrict__ deg) {
    int e = blockIdx.x * blockDim.x + threadIdx.x;
    if (e < NE) atomicAdd(&deg[ei[NE + e]], 1);
}

__global__ void scan_kernel(const int* __restrict__ deg, int* __restrict__ off) {
    __shared__ int wsum[32];
    __shared__ int carry_s;
    int tid = threadIdx.x, lane = tid & 31, wid = tid >> 5;
    if (tid == 0) { carry_s = 0; off[0] = 0; }
    __syncthreads();
    for (int base = 0; base < NN; base += 1024) {
        int i = base + tid;
        int v = (i < NN) ? deg[i] + 1 : 0;
        int x = v;
#pragma unroll
        for (int o = 1; o < 32; o <<= 1) {
            int t = __shfl_up_sync(0xffffffffu, x, o);
            if (lane >= o) x += t;
        }
        if (lane == 31) wsum[wid] = x;
        __syncthreads();
        if (wid == 0) {
            int y = wsum[lane];
#pragma unroll
            for (int o = 1; o < 32; o <<= 1) {
                int t = __shfl_up_sync(0xffffffffu, y, o);
                if (lane >= o) y += t;
            }
            wsum[lane] = y;
        }
        __syncthreads();
        int incl = x + (wid > 0 ? wsum[wid - 1] : 0) + carry_s;
        if (i < NN) off[i + 1] = incl;
        __syncthreads();
        if (tid == 1023) carry_s = incl;
        __syncthreads();
    }
}

__global__ void scatter_kernel(const int* __restrict__ ei, const int* __restrict__ off,
                               int* __restrict__ cnt, int* __restrict__ csr) {
    int e = blockIdx.x * blockDim.x + threadIdx.x;
    if (e < NE) {
        int d = ei[NE + e];
        int pos = off[d] + atomicAdd(&cnt[d], 1);
        csr[pos] = ei[e];
    } else if (e < NE + NN) {
        int n = e - NE;
        csr[off[n + 1] - 1] = n;  // self loop in last slot
    }
}

// ============ TF32 MMA GEMM: C[R,M] = A[R,K] @ B[K,M] ============
// Block: 128 rows x BN cols, 256 threads (8 warps), warp tile WM x WN.
// K must be a multiple of 16.
template <int BN, int WM, int WN>
__global__ void __launch_bounds__(256)
mma_gemm(int R, int K, int M,
         const float* __restrict__ A, const float* __restrict__ B,
         float* __restrict__ C) {
    constexpr int BM = 128, BK = 16;
    constexpr int ASTR = BK + 4;       // 20: conflict-free A reads
    constexpr int BSTR = BN + 8;       // k-stride lands 8 banks apart
    constexpr int MFRAG = WM / 16;
    constexpr int NFRAG = WN / 8;
    constexpr int WCOLS = BN / WN;

    __shared__ uint32_t As[BM * ASTR];
    __shared__ uint32_t Bs[BK * BSTR];

    const int tid = threadIdx.x;
    const int wid = tid >> 5, lane = tid & 31;
    const int wr = wid / WCOLS, wc = wid % WCOLS;
    const int row0 = blockIdx.x * BM;
    const int col0 = blockIdx.y * BN;
    const int lrow = lane >> 2, lcol = lane & 3;

    float c[MFRAG][NFRAG][4];
#pragma unroll
    for (int mf = 0; mf < MFRAG; mf++)
#pragma unroll
        for (int nf = 0; nf < NFRAG; nf++)
#pragma unroll
            for (int j = 0; j < 4; j++) c[mf][nf][j] = 0.f;

    for (int k0 = 0; k0 < K; k0 += BK) {
        // stage A tile (128 x 16), cvt to tf32
#pragma unroll
        for (int p = 0; p < 2; p++) {
            int i4 = tid * 2 + p;               // 0..511
            int r = i4 >> 2;
            int c4 = (i4 & 3) * 4;
            float4 v = make_float4(0.f, 0.f, 0.f, 0.f);
            if (row0 + r < R)
                v = *(const float4*)&A[(size_t)(row0 + r) * K + k0 + c4];
            As[r * ASTR + c4 + 0] = f2tf(v.x);
            As[r * ASTR + c4 + 1] = f2tf(v.y);
            As[r * ASTR + c4 + 2] = f2tf(v.z);
            As[r * ASTR + c4 + 3] = f2tf(v.w);
        }
        // stage B tile (16 x BN), cvt to tf32
        for (int i4 = tid; i4 < 4 * BN; i4 += 256) {
            int k = i4 / (BN / 4);
            int n4 = (i4 % (BN / 4)) * 4;
            float4 v = *(const float4*)&B[(size_t)(k0 + k) * M + col0 + n4];
            Bs[k * BSTR + n4 + 0] = f2tf(v.x);
            Bs[k * BSTR + n4 + 1] = f2tf(v.y);
            Bs[k * BSTR + n4 + 2] = f2tf(v.z);
            Bs[k * BSTR + n4 + 3] = f2tf(v.w);
        }
        __syncthreads();

#pragma unroll
        for (int ks = 0; ks < BK / 8; ks++) {
            uint32_t af[MFRAG][4], bf[NFRAG][2];
#pragma unroll
            for (int mf = 0; mf < MFRAG; mf++) {
                int br = wr * WM + mf * 16;
                af[mf][0] = As[(br + lrow) * ASTR + ks * 8 + lcol];
                af[mf][1] = As[(br + lrow + 8) * ASTR + ks * 8 + lcol];
                af[mf][2] = As[(br + lrow) * ASTR + ks * 8 + lcol + 4];
                af[mf][3] = As[(br + lrow + 8) * ASTR + ks * 8 + lcol + 4];
            }
#pragma unroll
            for (int nf = 0; nf < NFRAG; nf++) {
                int bc = wc * WN + nf * 8;
                bf[nf][0] = Bs[(ks * 8 + lcol) * BSTR + bc + lrow];
                bf[nf][1] = Bs[(ks * 8 + lcol + 4) * BSTR + bc + lrow];
            }
#pragma unroll
            for (int mf = 0; mf < MFRAG; mf++)
#pragma unroll
                for (int nf = 0; nf < NFRAG; nf++)
                    mma_tf32(c[mf][nf], af[mf], bf[nf]);
        }
        __syncthreads();
    }

    // epilogue
#pragma unroll
    for (int mf = 0; mf < MFRAG; mf++) {
#pragma unroll
        for (int nf = 0; nf < NFRAG; nf++) {
            int row = row0 + wr * WM + mf * 16 + lrow;
            int col = col0 + wc * WN + nf * 8 + 2 * lcol;
            if (row < R)
                *(float2*)&C[(size_t)row * M + col] = make_float2(c[mf][nf][0], c[mf][nf][1]);
            if (row + 8 < R)
                *(float2*)&C[(size_t)(row + 8) * M + col] = make_float2(c[mf][nf][2], c[mf][nf][3]);
        }
    }
}

// ================= attention coefficients: als/ald [N,H] =================
template <int H, int C>
__global__ void attn_kernel(const float* __restrict__ h,
                            const float* __restrict__ asr,
                            const float* __restrict__ adr,
                            float* __restrict__ als, float* __restrict__ ald) {
    int idx = blockIdx.x * blockDim.x + threadIdx.x;  // = n*H + head
    if (idx >= NN * H) return;
    int hd = idx % H;
    const float4* hv = (const float4*)(h + (size_t)idx * C);
    const float4* av = (const float4*)(asr + hd * C);
    const float4* dv = (const float4*)(adr + hd * C);
    float s = 0.f, d = 0.f;
#pragma unroll
    for (int i = 0; i < C / 4; i++) {
        float4 x = hv[i], a = av[i], b = dv[i];
        s += x.x * a.x + x.y * a.y + x.z * a.z + x.w * a.w;
        d += x.x * b.x + x.y * b.y + x.z * b.z + x.w * b.w;
    }
    als[idx] = s;
    ald[idx] = d;
}

// ================= CSR aggregation (softmax-normalized), fused bias/relu =======
template <bool RELU>
__global__ void __launch_bounds__(256)
agg8_kernel(const int* __restrict__ off, const int* __restrict__ csr,
            const float* __restrict__ h, const float* __restrict__ als,
            const float* __restrict__ ald, const float* __restrict__ b,
            float* __restrict__ out) {
    int node = blockIdx.x * 8 + (threadIdx.x >> 5);
    if (node >= NN) return;
    int lane = threadIdx.x & 31;
    int hl = lane >> 3, hh = hl + 4;
    float aldl = ald[node * 8 + hl], aldh = ald[node * 8 + hh];
    float4 accl = make_float4(0, 0, 0, 0), acch = make_float4(0, 0, 0, 0);
    float wsl = 0.f, wsh = 0.f;
    int s0 = off[node], s1 = off[node + 1];
    for (int i = s0; i < s1; i++) {
        int src = __ldg(&csr[i]);
        const float4* hs = (const float4*)(h + (size_t)src * 256);
        float el = __ldg(&als[src * 8 + hl]) + aldl;
        float eh = __ldg(&als[src * 8 + hh]) + aldh;
        el = el > 0.f ? el : NEG_SLOPE * el;
        eh = eh > 0.f ? eh : NEG_SLOPE * eh;
        float wl = __expf(el), wh = __expf(eh);
        float4 h1 = hs[lane], h2 = hs[lane + 32];
        accl.x += wl * h1.x; accl.y += wl * h1.y; accl.z += wl * h1.z; accl.w += wl * h1.w;
        acch.x += wh * h2.x; acch.y += wh * h2.y; acch.z += wh * h2.z; acch.w += wh * h2.w;
        wsl += wl; wsh += wh;
    }
    float invl = 1.f / wsl, invh = 1.f / wsh;
    float4 b1 = ((const float4*)b)[lane], b2 = ((const float4*)b)[lane + 32];
    float4 o1 = make_float4(accl.x * invl + b1.x, accl.y * invl + b1.y,
                            accl.z * invl + b1.z, accl.w * invl + b1.w);
    float4 o2 = make_float4(acch.x * invh + b2.x, acch.y * invh + b2.y,
                            acch.z * invh + b2.z, acch.w * invh + b2.w);
    if (RELU) {
        o1.x = fmaxf(o1.x, 0.f); o1.y = fmaxf(o1.y, 0.f);
        o1.z = fmaxf(o1.z, 0.f); o1.w = fmaxf(o1.w, 0.f);
        o2.x = fmaxf(o2.x, 0.f); o2.y = fmaxf(o2.y, 0.f);
        o2.z = fmaxf(o2.z, 0.f); o2.w = fmaxf(o2.w, 0.f);
    }
    float4* op = (float4*)(out + (size_t)node * 256);
    op[lane] = o1;
    op[lane + 32] = o2;
}

__global__ void __launch_bounds__(256)
agg1c32_kernel(const int* __restrict__ off, const int* __restrict__ csr,
               const float* __restrict__ h, const float* __restrict__ als,
               const float* __restrict__ ald, const float* __restrict__ b,
               float* __restrict__ out) {
    int node = blockIdx.x * 8 + (threadIdx.x >> 5);
    if (node >= NN) return;
    int lane = threadIdx.x & 31, sub = lane >> 3, col = lane & 7;
    float aldn = ald[node];
    float4 acc = make_float4(0, 0, 0, 0);
    float ws = 0.f;
    int s0 = off[node], s1 = off[node + 1];
    for (int i = s0 + sub; i < s1; i += 4) {
        int src = __ldg(&csr[i]);
        float e = __ldg(&als[src]) + aldn;
        e = e > 0.f ? e : NEG_SLOPE * e;
        float w = __expf(e);
        float4 hv = ((const float4*)(h + (size_t)src * 32))[col];
        acc.x += w * hv.x; acc.y += w * hv.y; acc.z += w * hv.z; acc.w += w * hv.w;
        ws += w;
    }
#pragma unroll
    for (int m = 8; m <= 16; m <<= 1) {
        acc.x += __shfl_xor_sync(0xffffffffu, acc.x, m);
        acc.y += __shfl_xor_sync(0xffffffffu, acc.y, m);
        acc.z += __shfl_xor_sync(0xffffffffu, acc.z, m);
        acc.w += __shfl_xor_sync(0xffffffffu, acc.w, m);
        ws    += __shfl_xor_sync(0xffffffffu, ws, m);
    }
    if (sub == 0) {
        float inv = 1.f / ws;
        float4 bb = ((const float4*)b)[col];
        float4 o = make_float4(acc.x * inv + bb.x, acc.y * inv + bb.y,
                               acc.z * inv + bb.z, acc.w * inv + bb.w);
        ((float4*)(out + (size_t)node * 32))[col] = o;
    }
}

__global__ void __launch_bounds__(256)
agg1c128_kernel(const int* __restrict__ off, const int* __restrict__ csr,
                const float* __restrict__ h, const float* __restrict__ als,
                const float* __restrict__ ald, const float* __restrict__ b,
                float* __restrict__ out) {
    int node = blockIdx.x * 8 + (threadIdx.x >> 5);
    if (node >= NN) return;
    int lane = threadIdx.x & 31;
    float aldn = ald[node];
    float4 acc = make_float4(0, 0, 0, 0);
    float ws = 0.f;
    int s0 = off[node], s1 = off[node + 1];
    for (int i = s0; i < s1; i++) {
        int src = __ldg(&csr[i]);
        float e = __ldg(&als[src]) + aldn;
        e = e > 0.f ? e : NEG_SLOPE * e;
        float w = __expf(e);
        float4 hv = ((const float4*)(h + (size_t)src * 128))[lane];
        acc.x += w * hv.x; acc.y += w * hv.y; acc.z += w * hv.z; acc.w += w * hv.w;
        ws += w;
    }
    float inv = 1.f / ws;
    float4 bb = ((const float4*)b)[lane];
    float4 o = make_float4(acc.x * inv + bb.x, acc.y * inv + bb.y,
                           acc.z * inv + bb.z, acc.w * inv + bb.w);
    ((float4*)(out + (size_t)node * 128))[lane] = o;
}

// ================= launch =================
static inline int ceil_div_i(long long a, long long b) { return (int)((a + b - 1) / b); }

extern "C" void kernel_launch(void* const* d_in, const int* in_sizes, int n_in,
                              void* d_out, int out_size) {
    const float* x = (const float*)d_in[0];
    const int* ei = (const int*)d_in[1];   // int32 (JAX x64 disabled)
    const float* W1 = (const float*)d_in[2];
    const float* as1 = (const float*)d_in[3];
    const float* ad1 = (const float*)d_in[4];
    const float* b1 = (const float*)d_in[5];
    const float* W2 = (const float*)d_in[6];
    const float* as2 = (const float*)d_in[7];
    const float* ad2 = (const float*)d_in[8];
    const float* b2 = (const float*)d_in[9];
    const float* W3 = (const float*)d_in[10];
    const float* as3 = (const float*)d_in[11];
    const float* ad3 = (const float*)d_in[12];
    const float* b3 = (const float*)d_in[13];
    const float* W4 = (const float*)d_in[14];
    const float* as4 = (const float*)d_in[15];
    const float* ad4 = (const float*)d_in[16];
    const float* b4 = (const float*)d_in[17];
    float* out = (float*)d_out;

    float *h, *z1, *z2, *r1, *als, *ald;
    int *deg, *cnt, *off, *csr;
    cudaGetSymbolAddress((void**)&h, g_h);
    cudaGetSymbolAddress((void**)&z1, g_z1);
    cudaGetSymbolAddress((void**)&z2, g_z2);
    cudaGetSymbolAddress((void**)&r1, g_r1);
    cudaGetSymbolAddress((void**)&als, g_als);
    cudaGetSymbolAddress((void**)&ald, g_ald);
    cudaGetSymbolAddress((void**)&deg, g_deg);
    cudaGetSymbolAddress((void**)&cnt, g_cnt);
    cudaGetSymbolAddress((void**)&off, g_off);
    cudaGetSymbolAddress((void**)&csr, g_csr);

    const int TPB = 256;
    const int rowBlocks = ceil_div_i(NN, 128);   // 391
    const int aggBlocks = ceil_div_i(NN, 8);

    // ---- CSR build (by dst), reused by all 4 layers ----
    cudaMemsetAsync(deg, 0, NN * sizeof(int), 0);
    cudaMemsetAsync(cnt, 0, NN * sizeof(int), 0);
    hist_kernel<<<ceil_div_i(NE, TPB), TPB>>>(ei, deg);
    scan_kernel<<<1, 1024>>>(deg, off);
    scatter_kernel<<<ceil_div_i(NE + NN, TPB), TPB>>>(ei, off, cnt, csr);

    // ===== Layer 1: 128 -> [8 x 32], relu =====
    mma_gemm<128, 64, 32><<<dim3(rowBlocks, 2), 256>>>(NN, 128, 256, x, W1, h);
    attn_kernel<8, 32><<<ceil_div_i((long long)NN * 8, TPB), TPB>>>(h, as1, ad1, als, ald);
    agg8_kernel<true><<<aggBlocks, TPB>>>(off, csr, h, als, ald, b1, z1);

    // ===== Layer 2: 256 -> 32 =====
    mma_gemm<32, 16, 32><<<dim3(rowBlocks, 1), 256>>>(NN, 256, 32, z1, W2, h);
    attn_kernel<1, 32><<<ceil_div_i(NN, TPB), TPB>>>(h, as2, ad2, als, ald);
    agg1c32_kernel<<<aggBlocks, TPB>>>(off, csr, h, als, ald, b2, z2);

    // ===== Layer 3: 32 -> [8 x 32], relu =====
    mma_gemm<128, 64, 32><<<dim3(rowBlocks, 2), 256>>>(NN, 32, 256, z2, W3, h);
    attn_kernel<8, 32><<<ceil_div_i((long long)NN * 8, TPB), TPB>>>(h, as3, ad3, als, ald);
    agg8_kernel<true><<<aggBlocks, TPB>>>(off, csr, h, als, ald, b3, r1);

    // ===== Layer 4: 256 -> 128 =====
    mma_gemm<128, 64, 32><<<dim3(rowBlocks, 1), 256>>>(NN, 256, 128, r1, W4, h);
    attn_kernel<1, 128><<<ceil_div_i(NN, TPB), TPB>>>(h, as4, ad4, als, ald);
    agg1c128_kernel<<<aggBlocks, TPB>>>(off, csr, h, als, ald, b4, out);
}

// round 12
// speedup vs baseline: 1.7780x; 1.3762x over previous
#include <cuda_runtime.h>
#include <cstdint>

#define NN 50000
#define NE 800000
constexpr float NEG_SLOPE = 0.2f;

// ---------------- scratch (device globals; no allocation) ----------------
__device__ float g_h  [NN * 256];
__device__ float g_z1 [NN * 256];
__device__ float g_z2 [NN * 32];
__device__ float g_r1 [NN * 256];
__device__ float g_als[NN * 8];
__device__ float g_ald[NN * 8];
__device__ int   g_deg[NN];
__device__ int   g_cnt[NN];
__device__ int   g_off[NN + 1];
__device__ int   g_csr[NE + NN];

// ---------------- helpers ----------------
__device__ __forceinline__ uint32_t f2tf(float f) {
    uint32_t r;
    asm("cvt.rna.tf32.f32 %0, %1;" : "=r"(r) : "f"(f));
    return r;
}
__device__ __forceinline__ void mma_tf32(float* c, const uint32_t* a, const uint32_t* b) {
    asm volatile(
        "mma.sync.aligned.m16n8k8.row.col.f32.tf32.tf32.f32 "
        "{%0,%1,%2,%3}, {%4,%5,%6,%7}, {%8,%9}, {%0,%1,%2,%3};"
        : "+f"(c[0]), "+f"(c[1]), "+f"(c[2]), "+f"(c[3])
        : "r"(a[0]), "r"(a[1]), "r"(a[2]), "r"(a[3]), "r"(b[0]), "r"(b[1]));
}
__device__ __forceinline__ uint32_t s2u(const void* p) {
    uint32_t a;
    asm("{ .reg .u64 t; cvta.to.shared.u64 t, %1; cvt.u32.u64 %0, t; }" : "=r"(a) : "l"(p));
    return a;
}
__device__ __forceinline__ void cp16(uint32_t dst, const void* src, int nbytes) {
    asm volatile("cp.async.ca.shared.global [%0], [%1], 16, %2;"
                 :: "r"(dst), "l"(src), "r"(nbytes) : "memory");
}
#define CP_COMMIT() asm volatile("cp.async.commit_group;" ::: "memory")
#define CP_WAIT0()  asm volatile("cp.async.wait_group 0;" ::: "memory")

// ================= CSR build =================
__global__ void hist_kernel(const int* __restrict__ ei, int* __restrict__ deg) {
    int e = blockIdx.x * blockDim.x + threadIdx.x;
    if (e < NE) atomicAdd(&deg[ei[NE + e]], 1);
}

__global__ void scan_kernel(const int* __restrict__ deg, int* __restrict__ off) {
    __shared__ int wsum[32];
    __shared__ int carry_s;
    int tid = threadIdx.x, lane = tid & 31, wid = tid >> 5;
    if (tid == 0) { carry_s = 0; off[0] = 0; }
    __syncthreads();
    for (int base = 0; base < NN; base += 1024) {
        int i = base + tid;
        int v = (i < NN) ? deg[i] + 1 : 0;
        int x = v;
#pragma unroll
        for (int o = 1; o < 32; o <<= 1) {
            int t = __shfl_up_sync(0xffffffffu, x, o);
            if (lane >= o) x += t;
        }
        if (lane == 31) wsum[wid] = x;
        __syncthreads();
        if (wid == 0) {
            int y = wsum[lane];
#pragma unroll
            for (int o = 1; o < 32; o <<= 1) {
                int t = __shfl_up_sync(0xffffffffu, y, o);
                if (lane >= o) y += t;
            }
            wsum[lane] = y;
        }
        __syncthreads();
        int incl = x + (wid > 0 ? wsum[wid - 1] : 0) + carry_s;
        if (i < NN) off[i + 1] = incl;
        __syncthreads();
        if (tid == 1023) carry_s = incl;
        __syncthreads();
    }
}

__global__ void scatter_kernel(const int* __restrict__ ei, const int* __restrict__ off,
                               int* __restrict__ cnt, int* __restrict__ csr) {
    int e = blockIdx.x * blockDim.x + threadIdx.x;
    if (e < NE) {
        int d = ei[NE + e];
        int pos = off[d] + atomicAdd(&cnt[d], 1);
        csr[pos] = ei[e];
    } else if (e < NE + NN) {
        int n = e - NE;
        csr[off[n + 1] - 1] = n;  // self loop in last slot
    }
}

// ============ TF32 MMA GEMM, cp.async double-buffered, optional fused attn ============
// Block: 128 rows x BN cols, 256 threads (8 warps), warp tile WM x WN. K % 32 == 0.
// FUSE (H=8,C=32 layers): each warp's 32-col span is one head; epilogue computes als/ald.
template <int BN, int WM, int WN, bool FUSE>
__global__ void __launch_bounds__(256, 2)
mma_gemm2(int R, int K, int M,
          const float* __restrict__ A, const float* __restrict__ B,
          float* __restrict__ C,
          const float* __restrict__ asr, const float* __restrict__ adr,
          float* __restrict__ als, float* __restrict__ ald) {
    constexpr int BM = 128, BK = 32;
    constexpr int ASTR = BK + 4;       // 36 u32: rows 144B apart (16B-aligned, conflict-free)
    constexpr int BSTR = BN + 8;
    constexpr int MFRAG = WM / 16, NFRAG = WN / 8, WCOLS = BN / WN;
    constexpr int ASZ = BM * ASTR;     // floats per buffer
    constexpr int BSZ = BK * BSTR;

    extern __shared__ float smem[];
    float* Asm = smem;                 // [2][ASZ]
    float* Bsm = smem + 2 * ASZ;       // [2][BSZ]

    const int tid = threadIdx.x;
    const int wid = tid >> 5, lane = tid & 31;
    const int wr = wid / WCOLS, wc = wid % WCOLS;
    const int row0 = blockIdx.x * BM;
    const int col0 = blockIdx.y * BN;
    const int lrow = lane >> 2, lcol = lane & 3;

    float c[MFRAG][NFRAG][4];
#pragma unroll
    for (int mf = 0; mf < MFRAG; mf++)
#pragma unroll
        for (int nf = 0; nf < NFRAG; nf++)
#pragma unroll
            for (int j = 0; j < 4; j++) c[mf][nf][j] = 0.f;

    auto issue = [&](int buf, int k0) {
        uint32_t abase = s2u(Asm + buf * ASZ);
#pragma unroll
        for (int p = 0; p < 4; p++) {
            int q = tid + p * 256;               // 1024 16B-chunks: 128 rows x 8
            int r = q >> 3, c4 = (q & 7) * 4;
            uint32_t dst = abase + (uint32_t)(r * ASTR + c4) * 4u;
            const float* src = &A[(size_t)(row0 + r) * K + k0 + c4];
            cp16(dst, src, (row0 + r < R) ? 16 : 0);
        }
        uint32_t bbase = s2u(Bsm + buf * BSZ);
#pragma unroll
        for (int p = 0; p < BN / 32; p++) {
            int q = tid + p * 256;               // BK*BN/4 chunks
            int kr = q / (BN / 4), n4 = (q % (BN / 4)) * 4;
            uint32_t dst = bbase + (uint32_t)(kr * BSTR + n4) * 4u;
            const float* src = &B[(size_t)(k0 + kr) * M + col0 + n4];
            cp16(dst, src, 16);
        }
        CP_COMMIT();
    };

    const int T = K / BK;
    issue(0, 0);
    for (int it = 0; it < T; it++) {
        int cur = it & 1;
        CP_WAIT0();
        __syncthreads();                          // all warps done with buf(cur^1) compute
        if (it + 1 < T) issue(cur ^ 1, (it + 1) * BK);

        const float* Af = Asm + cur * ASZ;
        const float* Bf = Bsm + cur * BSZ;
#pragma unroll
        for (int ks = 0; ks < BK / 8; ks++) {
            uint32_t af[MFRAG][4], bf[NFRAG][2];
#pragma unroll
            for (int mf = 0; mf < MFRAG; mf++) {
                int br = wr * WM + mf * 16;
                af[mf][0] = f2tf(Af[(br + lrow) * ASTR + ks * 8 + lcol]);
                af[mf][1] = f2tf(Af[(br + lrow + 8) * ASTR + ks * 8 + lcol]);
                af[mf][2] = f2tf(Af[(br + lrow) * ASTR + ks * 8 + lcol + 4]);
                af[mf][3] = f2tf(Af[(br + lrow + 8) * ASTR + ks * 8 + lcol + 4]);
            }
#pragma unroll
            for (int nf = 0; nf < NFRAG; nf++) {
                int bc = wc * WN + nf * 8;
                bf[nf][0] = f2tf(Bf[(ks * 8 + lcol) * BSTR + bc + lrow]);
                bf[nf][1] = f2tf(Bf[(ks * 8 + lcol + 4) * BSTR + bc + lrow]);
            }
#pragma unroll
            for (int mf = 0; mf < MFRAG; mf++)
#pragma unroll
                for (int nf = 0; nf < NFRAG; nf++)
                    mma_tf32(c[mf][nf], af[mf], bf[nf]);
        }
    }

    // ---- epilogue: store C ----
#pragma unroll
    for (int mf = 0; mf < MFRAG; mf++) {
#pragma unroll
        for (int nf = 0; nf < NFRAG; nf++) {
            int row = row0 + wr * WM + mf * 16 + lrow;
            int col = col0 + wc * WN + nf * 8 + 2 * lcol;
            if (row < R)
                *(float2*)&C[(size_t)row * M + col] = make_float2(c[mf][nf][0], c[mf][nf][1]);
            if (row + 8 < R)
                *(float2*)&C[(size_t)(row + 8) * M + col] = make_float2(c[mf][nf][2], c[mf][nf][3]);
        }
    }

    // ---- fused attention coefficients (H=8, C=32; warp == one head) ----
    if (FUSE) {
        int hd = (col0 >> 5) + wc;   // global head index
        float aS[MFRAG][2], aD[MFRAG][2];
#pragma unroll
        for (int mf = 0; mf < MFRAG; mf++) {
            aS[mf][0] = aS[mf][1] = 0.f;
            aD[mf][0] = aD[mf][1] = 0.f;
        }
#pragma unroll
        for (int nf = 0; nf < NFRAG; nf++) {
            int cl = nf * 8 + 2 * lcol;
            float s0 = __ldg(&asr[hd * 32 + cl]), s1 = __ldg(&asr[hd * 32 + cl + 1]);
            float d0 = __ldg(&adr[hd * 32 + cl]), d1 = __ldg(&adr[hd * 32 + cl + 1]);
#pragma unroll
            for (int mf = 0; mf < MFRAG; mf++) {
                aS[mf][0] += s0 * c[mf][nf][0] + s1 * c[mf][nf][1];
                aS[mf][1] += s0 * c[mf][nf][2] + s1 * c[mf][nf][3];
                aD[mf][0] += d0 * c[mf][nf][0] + d1 * c[mf][nf][1];
                aD[mf][1] += d0 * c[mf][nf][2] + d1 * c[mf][nf][3];
            }
        }
#pragma unroll
        for (int mf = 0; mf < MFRAG; mf++)
#pragma unroll
            for (int j = 0; j < 2; j++) {
                aS[mf][j] += __shfl_xor_sync(0xffffffffu, aS[mf][j], 1);
                aS[mf][j] += __shfl_xor_sync(0xffffffffu, aS[mf][j], 2);
                aD[mf][j] += __shfl_xor_sync(0xffffffffu, aD[mf][j], 1);
                aD[mf][j] += __shfl_xor_sync(0xffffffffu, aD[mf][j], 2);
            }
        if (lcol == 0) {
#pragma unroll
            for (int mf = 0; mf < MFRAG; mf++) {
                int row = row0 + wr * WM + mf * 16 + lrow;
                if (row < R) {
                    als[(size_t)row * 8 + hd] = aS[mf][0];
                    ald[(size_t)row * 8 + hd] = aD[mf][0];
                }
                if (row + 8 < R) {
                    als[(size_t)(row + 8) * 8 + hd] = aS[mf][1];
                    ald[(size_t)(row + 8) * 8 + hd] = aD[mf][1];
                }
            }
        }
    }
}

// ================= attention coefficients (H=1 layers) =================
template <int H, int C>
__global__ void attn_kernel(const float* __restrict__ h,
                            const float* __restrict__ asr,
                            const float* __restrict__ adr,
                            float* __restrict__ als, float* __restrict__ ald) {
    int idx = blockIdx.x * blockDim.x + threadIdx.x;  // = n*H + head
    if (idx >= NN * H) return;
    int hd = idx % H;
    const float4* hv = (const float4*)(h + (size_t)idx * C);
    const float4* av = (const float4*)(asr + hd * C);
    const float4* dv = (const float4*)(adr + hd * C);
    float s = 0.f, d = 0.f;
#pragma unroll
    for (int i = 0; i < C / 4; i++) {
        float4 x = hv[i], a = av[i], b = dv[i];
        s += x.x * a.x + x.y * a.y + x.z * a.z + x.w * a.w;
        d += x.x * b.x + x.y * b.y + x.z * b.z + x.w * b.w;
    }
    als[idx] = s;
    ald[idx] = d;
}

// ================= CSR aggregation (softmax-normalized), fused bias/relu =======
template <bool RELU>
__global__ void __launch_bounds__(256)
agg8_kernel(const int* __restrict__ off, const int* __restrict__ csr,
            const float* __restrict__ h, const float* __restrict__ als,
            const float* __restrict__ ald, const float* __restrict__ b,
            float* __restrict__ out) {
    int node = blockIdx.x * 8 + (threadIdx.x >> 5);
    if (node >= NN) return;
    int lane = threadIdx.x & 31;
    int hl = lane >> 3, hh = hl + 4;
    float aldl = ald[node * 8 + hl], aldh = ald[node * 8 + hh];
    float4 accl = make_float4(0, 0, 0, 0), acch = make_float4(0, 0, 0, 0);
    float wsl = 0.f, wsh = 0.f;
    int s0 = off[node], s1 = off[node + 1];
    for (int i = s0; i < s1; i++) {
        int src = __ldg(&csr[i]);
        const float4* hs = (const float4*)(h + (size_t)src * 256);
        float el = __ldg(&als[src * 8 + hl]) + aldl;
        float eh = __ldg(&als[src * 8 + hh]) + aldh;
        el = el > 0.f ? el : NEG_SLOPE * el;
        eh = eh > 0.f ? eh : NEG_SLOPE * eh;
        float wl = __expf(el), wh = __expf(eh);
        float4 h1 = hs[lane], h2 = hs[lane + 32];
        accl.x += wl * h1.x; accl.y += wl * h1.y; accl.z += wl * h1.z; accl.w += wl * h1.w;
        acch.x += wh * h2.x; acch.y += wh * h2.y; acch.z += wh * h2.z; acch.w += wh * h2.w;
        wsl += wl; wsh += wh;
    }
    float invl = 1.f / wsl, invh = 1.f / wsh;
    float4 b1 = ((const float4*)b)[lane], b2 = ((const float4*)b)[lane + 32];
    float4 o1 = make_float4(accl.x * invl + b1.x, accl.y * invl + b1.y,
                            accl.z * invl + b1.z, accl.w * invl + b1.w);
    float4 o2 = make_float4(acch.x * invh + b2.x, acch.y * invh + b2.y,
                            acch.z * invh + b2.z, acch.w * invh + b2.w);
    if (RELU) {
        o1.x = fmaxf(o1.x, 0.f); o1.y = fmaxf(o1.y, 0.f);
        o1.z = fmaxf(o1.z, 0.f); o1.w = fmaxf(o1.w, 0.f);
        o2.x = fmaxf(o2.x, 0.f); o2.y = fmaxf(o2.y, 0.f);
        o2.z = fmaxf(o2.z, 0.f); o2.w = fmaxf(o2.w, 0.f);
    }
    float4* op = (float4*)(out + (size_t)node * 256);
    op[lane] = o1;
    op[lane + 32] = o2;
}

__global__ void __launch_bounds__(256)
agg1c32_kernel(const int* __restrict__ off, const int* __restrict__ csr,
               const float* __restrict__ h, const float* __restrict__ als,
               const float* __restrict__ ald, const float* __restrict__ b,
               float* __restrict__ out) {
    int node = blockIdx.x * 8 + (threadIdx.x >> 5);
    if (node >= NN) return;
    int lane = threadIdx.x & 31, sub = lane >> 3, col = lane & 7;
    float aldn = ald[node];
    float4 acc = make_float4(0, 0, 0, 0);
    float ws = 0.f;
    int s0 = off[node], s1 = off[node + 1];
    for (int i = s0 + sub; i < s1; i += 4) {
        int src = __ldg(&csr[i]);
        float e = __ldg(&als[src]) + aldn;
        e = e > 0.f ? e : NEG_SLOPE * e;
        float w = __expf(e);
        float4 hv = ((const float4*)(h + (size_t)src * 32))[col];
        acc.x += w * hv.x; acc.y += w * hv.y; acc.z += w * hv.z; acc.w += w * hv.w;
        ws += w;
    }
#pragma unroll
    for (int m = 8; m <= 16; m <<= 1) {
        acc.x += __shfl_xor_sync(0xffffffffu, acc.x, m);
        acc.y += __shfl_xor_sync(0xffffffffu, acc.y, m);
        acc.z += __shfl_xor_sync(0xffffffffu, acc.z, m);
        acc.w += __shfl_xor_sync(0xffffffffu, acc.w, m);
        ws    += __shfl_xor_sync(0xffffffffu, ws, m);
    }
    if (sub == 0) {
        float inv = 1.f / ws;
        float4 bb = ((const float4*)b)[col];
        float4 o = make_float4(acc.x * inv + bb.x, acc.y * inv + bb.y,
                               acc.z * inv + bb.z, acc.w * inv + bb.w);
        ((float4*)(out + (size_t)node * 32))[col] = o;
    }
}

__global__ void __launch_bounds__(256)
agg1c128_kernel(const int* __restrict__ off, const int* __restrict__ csr,
                const float* __restrict__ h, const float* __restrict__ als,
                const float* __restrict__ ald, const float* __restrict__ b,
                float* __restrict__ out) {
    int node = blockIdx.x * 8 + (threadIdx.x >> 5);
    if (node >= NN) return;
    int lane = threadIdx.x & 31;
    float aldn = ald[node];
    float4 acc = make_float4(0, 0, 0, 0);
    float ws = 0.f;
    int s0 = off[node], s1 = off[node + 1];
    for (int i = s0; i < s1; i++) {
        int src = __ldg(&csr[i]);
        float e = __ldg(&als[src]) + aldn;
        e = e > 0.f ? e : NEG_SLOPE * e;
        float w = __expf(e);
        float4 hv = ((const float4*)(h + (size_t)src * 128))[lane];
        acc.x += w * hv.x; acc.y += w * hv.y; acc.z += w * hv.z; acc.w += w * hv.w;
        ws += w;
    }
    float inv = 1.f / ws;
    float4 bb = ((const float4*)b)[lane];
    float4 o = make_float4(acc.x * inv + bb.x, acc.y * inv + bb.y,
                           acc.z * inv + bb.z, acc.w * inv + bb.w);
    ((float4*)(out + (size_t)node * 128))[lane] = o;
}

// ================= launch =================
static inline int ceil_div_i(long long a, long long b) { return (int)((a + b - 1) / b); }

extern "C" void kernel_launch(void* const* d_in, const int* in_sizes, int n_in,
                              void* d_out, int out_size) {
    const float* x = (const float*)d_in[0];
    const int* ei = (const int*)d_in[1];   // int32 (JAX x64 disabled)
    const float* W1 = (const float*)d_in[2];
    const float* as1 = (const float*)d_in[3];
    const float* ad1 = (const float*)d_in[4];
    const float* b1 = (const float*)d_in[5];
    const float* W2 = (const float*)d_in[6];
    const float* as2 = (const float*)d_in[7];
    const float* ad2 = (const float*)d_in[8];
    const float* b2 = (const float*)d_in[9];
    const float* W3 = (const float*)d_in[10];
    const float* as3 = (const float*)d_in[11];
    const float* ad3 = (const float*)d_in[12];
    const float* b3 = (const float*)d_in[13];
    const float* W4 = (const float*)d_in[14];
    const float* as4 = (const float*)d_in[15];
    const float* ad4 = (const float*)d_in[16];
    const float* b4 = (const float*)d_in[17];
    float* out = (float*)d_out;

    float *h, *z1, *z2, *r1, *als, *ald;
    int *deg, *cnt, *off, *csr;
    cudaGetSymbolAddress((void**)&h, g_h);
    cudaGetSymbolAddress((void**)&z1, g_z1);
    cudaGetSymbolAddress((void**)&z2, g_z2);
    cudaGetSymbolAddress((void**)&r1, g_r1);
    cudaGetSymbolAddress((void**)&als, g_als);
    cudaGetSymbolAddress((void**)&ald, g_ald);
    cudaGetSymbolAddress((void**)&deg, g_deg);
    cudaGetSymbolAddress((void**)&cnt, g_cnt);
    cudaGetSymbolAddress((void**)&off, g_off);
    cudaGetSymbolAddress((void**)&csr, g_csr);

    const int TPB = 256;
    const int rowBlocks = ceil_div_i(NN, 128);   // 391
    const int aggBlocks = ceil_div_i(NN, 8);

    // dynamic smem: 2 buffers of A(128x36) + B(32 x (BN+8)) floats
    const int SZ128 = (2 * 128 * 36 + 2 * 32 * 136) * 4;  // 71680
    const int SZ32  = (2 * 128 * 36 + 2 * 32 * 40) * 4;   // 47104
    cudaFuncSetAttribute(mma_gemm2<128, 64, 32, true>,
                         cudaFuncAttributeMaxDynamicSharedMemorySize, SZ128);
    cudaFuncSetAttribute(mma_gemm2<128, 64, 32, false>,
                         cudaFuncAttributeMaxDynamicSharedMemorySize, SZ128);
    cudaFuncSetAttribute(mma_gemm2<32, 16, 32, false>,
                         cudaFuncAttributeMaxDynamicSharedMemorySize, SZ32);

    // ---- CSR build (by dst), reused by all 4 layers ----
    cudaMemsetAsync(deg, 0, NN * sizeof(int), 0);
    cudaMemsetAsync(cnt, 0, NN * sizeof(int), 0);
    hist_kernel<<<ceil_div_i(NE, TPB), TPB>>>(ei, deg);
    scan_kernel<<<1, 1024>>>(deg, off);
    scatter_kernel<<<ceil_div_i(NE + NN, TPB), TPB>>>(ei, off, cnt, csr);

    // ===== Layer 1: 128 -> [8 x 32], relu (attn fused) =====
    mma_gemm2<128, 64, 32, true><<<dim3(rowBlocks, 2), 256, SZ128>>>(
        NN, 128, 256, x, W1, h, as1, ad1, als, ald);
    agg8_kernel<true><<<aggBlocks, TPB>>>(off, csr, h, als, ald, b1, z1);

    // ===== Layer 2: 256 -> 32 =====
    mma_gemm2<32, 16, 32, false><<<dim3(rowBlocks, 1), 256, SZ32>>>(
        NN, 256, 32, z1, W2, h, nullptr, nullptr, nullptr, nullptr);
    attn_kernel<1, 32><<<ceil_div_i(NN, TPB), TPB>>>(h, as2, ad2, als, ald);
    agg1c32_kernel<<<aggBlocks, TPB>>>(off, csr, h, als, ald, b2, z2);

    // ===== Layer 3: 32 -> [8 x 32], relu (attn fused; K=32 single tile) =====
    mma_gemm2<128, 64, 32, true><<<dim3(rowBlocks, 2), 256, SZ128>>>(
        NN, 32, 256, z2, W3, h, as3, ad3, als, ald);
    agg8_kernel<true><<<aggBlocks, TPB>>>(off, csr, h, als, ald, b3, r1);

    // ===== Layer 4: 256 -> 128 =====
    mma_gemm2<128, 64, 32, false><<<dim3(rowBlocks, 1), 256, SZ128>>>(
        NN, 256, 128, r1, W4, h, nullptr, nullptr, nullptr, nullptr);
    attn_kernel<1, 128><<<ceil_div_i(NN, TPB), TPB>>>(h, as4, ad4, als, ald);
    agg1c128_kernel<<<aggBlocks, TPB>>>(off, csr, h, als, ald, b4, out);
}

// round 14
// speedup vs baseline: 1.9935x; 1.1212x over previous
#include <cuda_runtime.h>
#include <cuda_fp16.h>
#include <cstdint>

#define NN 50000
#define NE 800000
constexpr float NEG_SLOPE = 0.2f;

// ---------------- scratch (device globals; no allocation) ----------------
__device__ __half g_hh [NN * 256];   // transformed features, fp16 (gather payload)
__device__ float  g_z1 [NN * 256];
__device__ float  g_z2 [NN * 32];
__device__ float  g_r1 [NN * 256];
__device__ float  g_als[NN * 8];
__device__ float  g_ald[NN * 8];
__device__ int    g_deg[NN];
__device__ int    g_cnt[NN];
__device__ int    g_off[NN + 1];
__device__ int    g_csr[NE + NN];

// ---------------- helpers ----------------
__device__ __forceinline__ uint32_t f2tf(float f) {
    uint32_t r;
    asm("cvt.rna.tf32.f32 %0, %1;" : "=r"(r) : "f"(f));
    return r;
}
__device__ __forceinline__ void mma_tf32(float* c, const uint32_t* a, const uint32_t* b) {
    asm volatile(
        "mma.sync.aligned.m16n8k8.row.col.f32.tf32.tf32.f32 "
        "{%0,%1,%2,%3}, {%4,%5,%6,%7}, {%8,%9}, {%0,%1,%2,%3};"
        : "+f"(c[0]), "+f"(c[1]), "+f"(c[2]), "+f"(c[3])
        : "r"(a[0]), "r"(a[1]), "r"(a[2]), "r"(a[3]), "r"(b[0]), "r"(b[1]));
}
__device__ __forceinline__ uint32_t s2u(const void* p) {
    uint32_t a;
    asm("{ .reg .u64 t; cvta.to.shared.u64 t, %1; cvt.u32.u64 %0, t; }" : "=r"(a) : "l"(p));
    return a;
}
__device__ __forceinline__ void cp16(uint32_t dst, const void* src, int nbytes) {
    asm volatile("cp.async.ca.shared.global [%0], [%1], 16, %2;"
                 :: "r"(dst), "l"(src), "r"(nbytes) : "memory");
}
#define CP_COMMIT() asm volatile("cp.async.commit_group;" ::: "memory")
#define CP_WAIT0()  asm volatile("cp.async.wait_group 0;" ::: "memory")

// ================= CSR build =================
__global__ void hist_kernel(const int* __restrict__ ei, int* __restrict__ deg) {
    int e = blockIdx.x * blockDim.x + threadIdx.x;
    if (e < NE) atomicAdd(&deg[ei[NE + e]], 1);
}

__global__ void scan_kernel(const int* __restrict__ deg, int* __restrict__ off) {
    __shared__ int wsum[32];
    __shared__ int carry_s;
    int tid = threadIdx.x, lane = tid & 31, wid = tid >> 5;
    if (tid == 0) { carry_s = 0; off[0] = 0; }
    __syncthreads();
    for (int base = 0; base < NN; base += 1024) {
        int i = base + tid;
        int v = (i < NN) ? deg[i] + 1 : 0;
        int x = v;
#pragma unroll
        for (int o = 1; o < 32; o <<= 1) {
            int t = __shfl_up_sync(0xffffffffu, x, o);
            if (lane >= o) x += t;
        }
        if (lane == 31) wsum[wid] = x;
        __syncthreads();
        if (wid == 0) {
            int y = wsum[lane];
#pragma unroll
            for (int o = 1; o < 32; o <<= 1) {
                int t = __shfl_up_sync(0xffffffffu, y, o);
                if (lane >= o) y += t;
            }
            wsum[lane] = y;
        }
        __syncthreads();
        int incl = x + (wid > 0 ? wsum[wid - 1] : 0) + carry_s;
        if (i < NN) off[i + 1] = incl;
        __syncthreads();
        if (tid == 1023) carry_s = incl;
        __syncthreads();
    }
}

__global__ void scatter_kernel(const int* __restrict__ ei, const int* __restrict__ off,
                               int* __restrict__ cnt, int* __restrict__ csr) {
    int e = blockIdx.x * blockDim.x + threadIdx.x;
    if (e < NE) {
        int d = ei[NE + e];
        int pos = off[d] + atomicAdd(&cnt[d], 1);
        csr[pos] = ei[e];
    } else if (e < NE + NN) {
        int n = e - NE;
        csr[off[n + 1] - 1] = n;  // self loop in last slot
    }
}

// ============ TF32 MMA GEMM, cp.async double-buffered, fp16 output, fused attn ========
// Block: 128 rows x BN cols, 256 threads (8 warps), warp tile WM x WN. K % 32 == 0.
// H > 0: fuse attn coefficients (warp's 32-col span = one head; als stride H).
template <int BN, int WM, int WN, int H>
__global__ void __launch_bounds__(256, 2)
mma_gemm2(int R, int K, int M,
          const float* __restrict__ A, const float* __restrict__ B,
          __half* __restrict__ C,
          const float* __restrict__ asr, const float* __restrict__ adr,
          float* __restrict__ als, float* __restrict__ ald) {
    constexpr int BM = 128, BK = 32;
    constexpr int ASTR = BK + 4;
    constexpr int BSTR = BN + 8;
    constexpr int MFRAG = WM / 16, NFRAG = WN / 8, WCOLS = BN / WN;
    constexpr int ASZ = BM * ASTR;
    constexpr int BSZ = BK * BSTR;

    extern __shared__ float smem[];
    float* Asm = smem;
    float* Bsm = smem + 2 * ASZ;

    const int tid = threadIdx.x;
    const int wid = tid >> 5, lane = tid & 31;
    const int wr = wid / WCOLS, wc = wid % WCOLS;
    const int row0 = blockIdx.x * BM;
    const int col0 = blockIdx.y * BN;
    const int lrow = lane >> 2, lcol = lane & 3;

    float c[MFRAG][NFRAG][4];
#pragma unroll
    for (int mf = 0; mf < MFRAG; mf++)
#pragma unroll
        for (int nf = 0; nf < NFRAG; nf++)
#pragma unroll
            for (int j = 0; j < 4; j++) c[mf][nf][j] = 0.f;

    auto issue = [&](int buf, int k0) {
        uint32_t abase = s2u(Asm + buf * ASZ);
#pragma unroll
        for (int p = 0; p < 4; p++) {
            int q = tid + p * 256;
            int r = q >> 3, c4 = (q & 7) * 4;
            uint32_t dst = abase + (uint32_t)(r * ASTR + c4) * 4u;
            const float* src = &A[(size_t)(row0 + r) * K + k0 + c4];
            cp16(dst, src, (row0 + r < R) ? 16 : 0);
        }
        uint32_t bbase = s2u(Bsm + buf * BSZ);
#pragma unroll
        for (int p = 0; p < BN / 32; p++) {
            int q = tid + p * 256;
            int kr = q / (BN / 4), n4 = (q % (BN / 4)) * 4;
            uint32_t dst = bbase + (uint32_t)(kr * BSTR + n4) * 4u;
            const float* src = &B[(size_t)(k0 + kr) * M + col0 + n4];
            cp16(dst, src, 16);
        }
        CP_COMMIT();
    };

    const int T = K / BK;
    issue(0, 0);
    for (int it = 0; it < T; it++) {
        int cur = it & 1;
        CP_WAIT0();
        __syncthreads();
        if (it + 1 < T) issue(cur ^ 1, (it + 1) * BK);

        const float* Af = Asm + cur * ASZ;
        const float* Bf = Bsm + cur * BSZ;
#pragma unroll
        for (int ks = 0; ks < BK / 8; ks++) {
            uint32_t af[MFRAG][4], bf[NFRAG][2];
#pragma unroll
            for (int mf = 0; mf < MFRAG; mf++) {
                int br = wr * WM + mf * 16;
                af[mf][0] = f2tf(Af[(br + lrow) * ASTR + ks * 8 + lcol]);
                af[mf][1] = f2tf(Af[(br + lrow + 8) * ASTR + ks * 8 + lcol]);
                af[mf][2] = f2tf(Af[(br + lrow) * ASTR + ks * 8 + lcol + 4]);
                af[mf][3] = f2tf(Af[(br + lrow + 8) * ASTR + ks * 8 + lcol + 4]);
            }
#pragma unroll
            for (int nf = 0; nf < NFRAG; nf++) {
                int bc = wc * WN + nf * 8;
                bf[nf][0] = f2tf(Bf[(ks * 8 + lcol) * BSTR + bc + lrow]);
                bf[nf][1] = f2tf(Bf[(ks * 8 + lcol + 4) * BSTR + bc + lrow]);
            }
#pragma unroll
            for (int mf = 0; mf < MFRAG; mf++)
#pragma unroll
                for (int nf = 0; nf < NFRAG; nf++)
                    mma_tf32(c[mf][nf], af[mf], bf[nf]);
        }
    }

    // ---- epilogue: store C as fp16 ----
#pragma unroll
    for (int mf = 0; mf < MFRAG; mf++) {
#pragma unroll
        for (int nf = 0; nf < NFRAG; nf++) {
            int row = row0 + wr * WM + mf * 16 + lrow;
            int col = col0 + wc * WN + nf * 8 + 2 * lcol;
            if (row < R)
                *(__half2*)&C[(size_t)row * M + col] =
                    __floats2half2_rn(c[mf][nf][0], c[mf][nf][1]);
            if (row + 8 < R)
                *(__half2*)&C[(size_t)(row + 8) * M + col] =
                    __floats2half2_rn(c[mf][nf][2], c[mf][nf][3]);
        }
    }

    // ---- fused attention coefficients (per-head 32-col spans; stride H) ----
    if (H > 0) {
        int hd = (col0 >> 5) + wc;
        float aS[MFRAG][2], aD[MFRAG][2];
#pragma unroll
        for (int mf = 0; mf < MFRAG; mf++) {
            aS[mf][0] = aS[mf][1] = 0.f;
            aD[mf][0] = aD[mf][1] = 0.f;
        }
#pragma unroll
        for (int nf = 0; nf < NFRAG; nf++) {
            int cl = nf * 8 + 2 * lcol;
            float s0 = __ldg(&asr[hd * 32 + cl]), s1 = __ldg(&asr[hd * 32 + cl + 1]);
            float d0 = __ldg(&adr[hd * 32 + cl]), d1 = __ldg(&adr[hd * 32 + cl + 1]);
#pragma unroll
            for (int mf = 0; mf < MFRAG; mf++) {
                aS[mf][0] += s0 * c[mf][nf][0] + s1 * c[mf][nf][1];
                aS[mf][1] += s0 * c[mf][nf][2] + s1 * c[mf][nf][3];
                aD[mf][0] += d0 * c[mf][nf][0] + d1 * c[mf][nf][1];
                aD[mf][1] += d0 * c[mf][nf][2] + d1 * c[mf][nf][3];
            }
        }
#pragma unroll
        for (int mf = 0; mf < MFRAG; mf++)
#pragma unroll
            for (int j = 0; j < 2; j++) {
                aS[mf][j] += __shfl_xor_sync(0xffffffffu, aS[mf][j], 1);
                aS[mf][j] += __shfl_xor_sync(0xffffffffu, aS[mf][j], 2);
                aD[mf][j] += __shfl_xor_sync(0xffffffffu, aD[mf][j], 1);
                aD[mf][j] += __shfl_xor_sync(0xffffffffu, aD[mf][j], 2);
            }
        if (lcol == 0) {
#pragma unroll
            for (int mf = 0; mf < MFRAG; mf++) {
                int row = row0 + wr * WM + mf * 16 + lrow;
                if (row < R) {
                    als[(size_t)row * H + hd] = aS[mf][0];
                    ald[(size_t)row * H + hd] = aD[mf][0];
                }
                if (row + 8 < R) {
                    als[(size_t)(row + 8) * H + hd] = aS[mf][1];
                    ald[(size_t)(row + 8) * H + hd] = aD[mf][1];
                }
            }
        }
    }
}

// ================= attention coefficients, layer 4 (H=1, C=128, fp16 h) ==========
__global__ void __launch_bounds__(256)
attn_h128_kernel(const __half* __restrict__ hh, const float* __restrict__ asr,
                 const float* __restrict__ adr, float* __restrict__ als,
                 float* __restrict__ ald) {
    int node = blockIdx.x * 8 + (threadIdx.x >> 5);
    if (node >= NN) return;
    int lane = threadIdx.x & 31;
    uint2 hv = *(const uint2*)(hh + (size_t)node * 128 + lane * 4);
    float2 p0 = __half22float2(*(__half2*)&hv.x);
    float2 p1 = __half22float2(*(__half2*)&hv.y);
    float4 a = *(const float4*)&asr[lane * 4];
    float4 d = *(const float4*)&adr[lane * 4];
    float s = p0.x * a.x + p0.y * a.y + p1.x * a.z + p1.y * a.w;
    float dd = p0.x * d.x + p0.y * d.y + p1.x * d.z + p1.y * d.w;
#pragma unroll
    for (int m = 16; m >= 1; m >>= 1) {
        s += __shfl_xor_sync(0xffffffffu, s, m);
        dd += __shfl_xor_sync(0xffffffffu, dd, m);
    }
    if (lane == 0) {
        als[node] = s;
        ald[node] = dd;
    }
}

// ================= CSR aggregation (fp16 gather), fused bias/relu =================
// H=8, C=32: warp per node; lane owns 8 cols [lane*8, lane*8+8); head = lane>>2.
template <bool RELU>
__global__ void __launch_bounds__(256)
agg8h_kernel(const int* __restrict__ off, const int* __restrict__ csr,
             const __half* __restrict__ hh, const float* __restrict__ als,
             const float* __restrict__ ald, const float* __restrict__ b,
             float* __restrict__ out) {
    int node = blockIdx.x * 8 + (threadIdx.x >> 5);
    if (node >= NN) return;
    int lane = threadIdx.x & 31;
    int hd = lane >> 2;
    float aldh = __ldg(&ald[node * 8 + hd]);
    float acc[8] = {0.f, 0.f, 0.f, 0.f, 0.f, 0.f, 0.f, 0.f};
    float ws = 0.f;
    int s0 = off[node], s1 = off[node + 1];
    for (int i = s0; i < s1; i++) {
        int src = __ldg(&csr[i]);
        float e = __ldg(&als[src * 8 + hd]) + aldh;
        e = e > 0.f ? e : NEG_SLOPE * e;
        float w = __expf(e);
        uint4 hv = *(const uint4*)(hh + (size_t)src * 256 + lane * 8);
        float2 p0 = __half22float2(*(__half2*)&hv.x);
        float2 p1 = __half22float2(*(__half2*)&hv.y);
        float2 p2 = __half22float2(*(__half2*)&hv.z);
        float2 p3 = __half22float2(*(__half2*)&hv.w);
        acc[0] += w * p0.x; acc[1] += w * p0.y;
        acc[2] += w * p1.x; acc[3] += w * p1.y;
        acc[4] += w * p2.x; acc[5] += w * p2.y;
        acc[6] += w * p3.x; acc[7] += w * p3.y;
        ws += w;
    }
    float inv = 1.f / ws;
    float4 b0 = *(const float4*)&b[lane * 8];
    float4 b1 = *(const float4*)&b[lane * 8 + 4];
    float4 o0 = make_float4(acc[0] * inv + b0.x, acc[1] * inv + b0.y,
                            acc[2] * inv + b0.z, acc[3] * inv + b0.w);
    float4 o1 = make_float4(acc[4] * inv + b1.x, acc[5] * inv + b1.y,
                            acc[6] * inv + b1.z, acc[7] * inv + b1.w);
    if (RELU) {
        o0.x = fmaxf(o0.x, 0.f); o0.y = fmaxf(o0.y, 0.f);
        o0.z = fmaxf(o0.z, 0.f); o0.w = fmaxf(o0.w, 0.f);
        o1.x = fmaxf(o1.x, 0.f); o1.y = fmaxf(o1.y, 0.f);
        o1.z = fmaxf(o1.z, 0.f); o1.w = fmaxf(o1.w, 0.f);
    }
    float4* op = (float4*)(out + (size_t)node * 256 + lane * 8);
    op[0] = o0;
    op[1] = o1;
}

// H=1, C=32: warp per node, 4 edges/iter (8 lanes per edge), butterfly combine.
__global__ void __launch_bounds__(256)
agg1c32h_kernel(const int* __restrict__ off, const int* __restrict__ csr,
                const __half* __restrict__ hh, const float* __restrict__ als,
                const float* __restrict__ ald, const float* __restrict__ b,
                float* __restrict__ out) {
    int node = blockIdx.x * 8 + (threadIdx.x >> 5);
    if (node >= NN) return;
    int lane = threadIdx.x & 31, sub = lane >> 3, col = lane & 7;
    float aldn = ald[node];
    float acc[4] = {0.f, 0.f, 0.f, 0.f};
    float ws = 0.f;
    int s0 = off[node], s1 = off[node + 1];
    for (int i = s0 + sub; i < s1; i += 4) {
        int src = __ldg(&csr[i]);
        float e = __ldg(&als[src]) + aldn;
        e = e > 0.f ? e : NEG_SLOPE * e;
        float w = __expf(e);
        uint2 hv = *(const uint2*)(hh + (size_t)src * 32 + col * 4);
        float2 p0 = __half22float2(*(__half2*)&hv.x);
        float2 p1 = __half22float2(*(__half2*)&hv.y);
        acc[0] += w * p0.x; acc[1] += w * p0.y;
        acc[2] += w * p1.x; acc[3] += w * p1.y;
        ws += w;
    }
#pragma unroll
    for (int m = 8; m <= 16; m <<= 1) {
#pragma unroll
        for (int j = 0; j < 4; j++)
            acc[j] += __shfl_xor_sync(0xffffffffu, acc[j], m);
        ws += __shfl_xor_sync(0xffffffffu, ws, m);
    }
    if (sub == 0) {
        float inv = 1.f / ws;
        float4 bb = *(const float4*)&b[col * 4];
        float4 o = make_float4(acc[0] * inv + bb.x, acc[1] * inv + bb.y,
                               acc[2] * inv + bb.z, acc[3] * inv + bb.w);
        *(float4*)&out[(size_t)node * 32 + col * 4] = o;
    }
}

// H=1, C=128: warp per node, lane owns 4 cols.
__global__ void __launch_bounds__(256)
agg1c128h_kernel(const int* __restrict__ off, const int* __restrict__ csr,
                 const __half* __restrict__ hh, const float* __restrict__ als,
                 const float* __restrict__ ald, const float* __restrict__ b,
                 float* __restrict__ out) {
    int node = blockIdx.x * 8 + (threadIdx.x >> 5);
    if (node >= NN) return;
    int lane = threadIdx.x & 31;
    float aldn = ald[node];
    float acc[4] = {0.f, 0.f, 0.f, 0.f};
    float ws = 0.f;
    int s0 = off[node], s1 = off[node + 1];
    for (int i = s0; i < s1; i++) {
        int src = __ldg(&csr[i]);
        float e = __ldg(&als[src]) + aldn;
        e = e > 0.f ? e : NEG_SLOPE * e;
        float w = __expf(e);
        uint2 hv = *(const uint2*)(hh + (size_t)src * 128 + lane * 4);
        float2 p0 = __half22float2(*(__half2*)&hv.x);
        float2 p1 = __half22float2(*(__half2*)&hv.y);
        acc[0] += w * p0.x; acc[1] += w * p0.y;
        acc[2] += w * p1.x; acc[3] += w * p1.y;
        ws += w;
    }
    float inv = 1.f / ws;
    float4 bb = *(const float4*)&b[lane * 4];
    float4 o = make_float4(acc[0] * inv + bb.x, acc[1] * inv + bb.y,
                           acc[2] * inv + bb.z, acc[3] * inv + bb.w);
    *(float4*)&out[(size_t)node * 128 + lane * 4] = o;
}

// ================= launch =================
static inline int ceil_div_i(long long a, long long b) { return (int)((a + b - 1) / b); }

extern "C" void kernel_launch(void* const* d_in, const int* in_sizes, int n_in,
                              void* d_out, int out_size) {
    const float* x = (const float*)d_in[0];
    const int* ei = (const int*)d_in[1];   // int32 (JAX x64 disabled)
    const float* W1 = (const float*)d_in[2];
    const float* as1 = (const float*)d_in[3];
    const float* ad1 = (const float*)d_in[4];
    const float* b1 = (const float*)d_in[5];
    const float* W2 = (const float*)d_in[6];
    const float* as2 = (const float*)d_in[7];
    const float* ad2 = (const float*)d_in[8];
    const float* b2 = (const float*)d_in[9];
    const float* W3 = (const float*)d_in[10];
    const float* as3 = (const float*)d_in[11];
    const float* ad3 = (const float*)d_in[12];
    const float* b3 = (const float*)d_in[13];
    const float* W4 = (const float*)d_in[14];
    const float* as4 = (const float*)d_in[15];
    const float* ad4 = (const float*)d_in[16];
    const float* b4 = (const float*)d_in[17];
    float* out = (float*)d_out;

    __half* hh;
    float *z1, *z2, *r1, *als, *ald;
    int *deg, *cnt, *off, *csr;
    cudaGetSymbolAddress((void**)&hh, g_hh);
    cudaGetSymbolAddress((void**)&z1, g_z1);
    cudaGetSymbolAddress((void**)&z2, g_z2);
    cudaGetSymbolAddress((void**)&r1, g_r1);
    cudaGetSymbolAddress((void**)&als, g_als);
    cudaGetSymbolAddress((void**)&ald, g_ald);
    cudaGetSymbolAddress((void**)&deg, g_deg);
    cudaGetSymbolAddress((void**)&cnt, g_cnt);
    cudaGetSymbolAddress((void**)&off, g_off);
    cudaGetSymbolAddress((void**)&csr, g_csr);

    const int TPB = 256;
    const int rowBlocks = ceil_div_i(NN, 128);   // 391
    const int aggBlocks = ceil_div_i(NN, 8);

    const int SZ128 = (2 * 128 * 36 + 2 * 32 * 136) * 4;
    const int SZ32  = (2 * 128 * 36 + 2 * 32 * 40) * 4;
    cudaFuncSetAttribute(mma_gemm2<128, 64, 32, 8>,
                         cudaFuncAttributeMaxDynamicSharedMemorySize, SZ128);
    cudaFuncSetAttribute(mma_gemm2<128, 64, 32, 0>,
                         cudaFuncAttributeMaxDynamicSharedMemorySize, SZ128);
    cudaFuncSetAttribute(mma_gemm2<32, 16, 32, 1>,
                         cudaFuncAttributeMaxDynamicSharedMemorySize, SZ32);

    // ---- CSR build (by dst), reused by all 4 layers ----
    cudaMemsetAsync(deg, 0, NN * sizeof(int), 0);
    cudaMemsetAsync(cnt, 0, NN * sizeof(int), 0);
    hist_kernel<<<ceil_div_i(NE, TPB), TPB>>>(ei, deg);
    scan_kernel<<<1, 1024>>>(deg, off);
    scatter_kernel<<<ceil_div_i(NE + NN, TPB), TPB>>>(ei, off, cnt, csr);

    // ===== Layer 1: 128 -> [8 x 32], relu (attn fused) =====
    mma_gemm2<128, 64, 32, 8><<<dim3(rowBlocks, 2), 256, SZ128>>>(
        NN, 128, 256, x, W1, hh, as1, ad1, als, ald);
    agg8h_kernel<true><<<aggBlocks, TPB>>>(off, csr, hh, als, ald, b1, z1);

    // ===== Layer 2: 256 -> 32 (attn fused) =====
    mma_gemm2<32, 16, 32, 1><<<dim3(rowBlocks, 1), 256, SZ32>>>(
        NN, 256, 32, z1, W2, hh, as2, ad2, als, ald);
    agg1c32h_kernel<<<aggBlocks, TPB>>>(off, csr, hh, als, ald, b2, z2);

    // ===== Layer 3: 32 -> [8 x 32], relu (attn fused; K=32 single tile) =====
    mma_gemm2<128, 64, 32, 8><<<dim3(rowBlocks, 2), 256, SZ128>>>(
        NN, 32, 256, z2, W3, hh, as3, ad3, als, ald);
    agg8h_kernel<true><<<aggBlocks, TPB>>>(off, csr, hh, als, ald, b3, r1);

    // ===== Layer 4: 256 -> 128 =====
    mma_gemm2<128, 64, 32, 0><<<dim3(rowBlocks, 1), 256, SZ128>>>(
        NN, 256, 128, r1, W4, hh, nullptr, nullptr, nullptr, nullptr);
    attn_h128_kernel<<<aggBlocks, TPB>>>(hh, as4, ad4, als, ald);
    agg1c128h_kernel<<<aggBlocks, TPB>>>(off, csr, hh, als, ald, b4, out);
}